// round 14
// baseline (speedup 1.0000x reference)
#include <cuda_runtime.h>
#include <cuda_fp16.h>
#include <math.h>
#include <stdint.h>

#define BB 2
#define TT 2048
#define DD 1024
#define HH 16
#define HD 64
#define MROWS (BB*TT)   // 4096

// Scratch (allocation-free rule: device globals), all fp16 operands
__device__ __half g_q[BB*HH*TT*HD];    // [b][h][t][hd], pre-scaled by log2e/32
__device__ __half g_k[BB*HH*TT*HD];    // [b][h][t][hd]
__device__ __half g_v[BB*HH*TT*HD];    // [b][h][hd][t]  TRANSPOSED
__device__ __half g_x16[MROWS*DD];     // x as fp16
__device__ __half g_wqT[3*DD*DD];      // [3D][D] transposed w_qkv fp16
__device__ __half g_woT[DD*DD];        // [D][D]  transposed w_o  fp16
__device__ __half g_y16[MROWS*DD];     // attention out fp16 [b][t][h*64+hd]

#define NEG_INF __int_as_float(0xff800000)

__device__ __forceinline__ unsigned smem_u32(const void* p) {
    return (unsigned)__cvta_generic_to_shared(p);
}

// ---------------------------------------------------------------------------
// Prep: convert x to fp16
// ---------------------------------------------------------------------------
__global__ __launch_bounds__(256)
void conv_x_kernel(const float* __restrict__ x)
{
    int i = (blockIdx.x * 256 + threadIdx.x) * 4;
    float4 v = *(const float4*)(x + i);
    *(__half2*)(g_x16 + i)     = __floats2half2_rn(v.x, v.y);
    *(__half2*)(g_x16 + i + 2) = __floats2half2_rn(v.z, v.w);
}

// ---------------------------------------------------------------------------
// Prep: transpose + convert weights. dst[c][r] = fp16(src[r][c]); src RxC.
// ---------------------------------------------------------------------------
template<int WHICH>
__global__ __launch_bounds__(256)
void transpose_half_kernel(const float* __restrict__ src, int R, int C)
{
    __half* dst = (WHICH == 0) ? g_wqT : g_woT;
    __shared__ float tile[32][33];
    const int r0 = blockIdx.y * 32, c0 = blockIdx.x * 32;
    const int tx = threadIdx.x & 31, ty = threadIdx.x >> 5;
#pragma unroll
    for (int i = 0; i < 32; i += 8)
        tile[ty + i][tx] = src[(size_t)(r0 + ty + i) * C + c0 + tx];
    __syncthreads();
#pragma unroll
    for (int i = 0; i < 32; i += 8)
        dst[(size_t)(c0 + ty + i) * R + r0 + tx] = __float2half_rn(tile[tx][ty + i]);
}

// ---------------------------------------------------------------------------
// FP16 tensor-core GEMM: C[M,N] = A[M,K] @ Bt[N,K]^T + bias, fp32 accumulate.
// 128x128 tile, 4 warps (64x64 warp tiles — CUTLASS sm80 shape), K-chunk 64,
// 3-stage cp.async. m16n8k16 f16 mma; smem row stride 72 halves.
// MODE 0: A=g_x16, Bt=g_wqT -> scatter q (scaled)/k -> [B,H,T,HD], v -> [B,H,HD,T]
// MODE 1: A=g_y16, Bt=g_woT -> fp32 C row-major (final output)
// ---------------------------------------------------------------------------
#define SROWH 72
#define HBUF (128*SROWH)   // halves per tile buffer

template<int MODE>
__global__ __launch_bounds__(128, 2)
void gemm_fp16(const float* __restrict__ bias, float* __restrict__ C, int N)
{
    extern __shared__ __half hsm[];
    __half* Asm = hsm;              // 3 buffers
    __half* Bsm = hsm + 3 * HBUF;   // 3 buffers
    const int K = DD;

    const int tid  = threadIdx.x;
    const int lane = tid & 31, warp = tid >> 5;   // 4 warps
    const int wm = warp >> 1;       // 0..1
    const int wn = warp & 1;        // 0..1
    const int bm = blockIdx.y * 128, bn = blockIdx.x * 128;

    const __half* Aeff = (MODE == 0) ? g_x16 : g_y16;
    const __half* Bt   = (MODE == 0) ? g_wqT : g_woT;

    float acc[4][8][4];
#pragma unroll
    for (int a = 0; a < 4; a++)
#pragma unroll
        for (int b = 0; b < 8; b++)
#pragma unroll
            for (int c = 0; c < 4; c++) acc[a][b][c] = 0.f;

    auto copy_chunk = [&](int ck, int buf) {
        const __half* ag = Aeff + (size_t)bm * K + ck * 64;
        const __half* bg = Bt   + (size_t)bn * K + ck * 64;
        __half* as = Asm + buf * HBUF;
        __half* bs = Bsm + buf * HBUF;
        const int r = tid;   // 0..127
#pragma unroll
        for (int q = 0; q < 8; q++) {
            asm volatile("cp.async.cg.shared.global [%0], [%1], 16;\n"
                         :: "r"(smem_u32(as + r * SROWH + q * 8)),
                            "l"(ag + (size_t)r * K + q * 8) : "memory");
            asm volatile("cp.async.cg.shared.global [%0], [%1], 16;\n"
                         :: "r"(smem_u32(bs + r * SROWH + q * 8)),
                            "l"(bg + (size_t)r * K + q * 8) : "memory");
        }
        asm volatile("cp.async.commit_group;\n" ::: "memory");
    };

    copy_chunk(0, 0);
    copy_chunk(1, 1);

    const int j8  = lane & 7;
    const int sub = lane >> 3;

    int cur = 0;
    const int NCK = K / 64;   // 16
    for (int ck = 0; ck < NCK; ck++) {
        if (ck < NCK - 1) { asm volatile("cp.async.wait_group 1;\n" ::: "memory"); }
        else              { asm volatile("cp.async.wait_group 0;\n" ::: "memory"); }
        __syncthreads();
        if (ck + 2 < NCK) {
            int pf = cur + 2; if (pf >= 3) pf -= 3;
            copy_chunk(ck + 2, pf);
        }

        const __half* as = Asm + cur * HBUF;
        const __half* bs = Bsm + cur * HBUF;

#pragma unroll
        for (int ks = 0; ks < 4; ks++) {          // 4 x k16 per 64-chunk
            const int k16 = ks * 16;
            uint32_t a[4][4];
#pragma unroll
            for (int mf = 0; mf < 4; mf++) {
                const int row = wm * 64 + mf * 16 + (sub & 1) * 8 + j8;
                const int col = k16 + (sub >> 1) * 8;
                unsigned addr = smem_u32(as + row * SROWH + col);
                asm volatile("ldmatrix.sync.aligned.m8n8.x4.shared.b16 {%0,%1,%2,%3}, [%4];\n"
                             : "=r"(a[mf][0]), "=r"(a[mf][1]), "=r"(a[mf][2]), "=r"(a[mf][3])
                             : "r"(addr));
            }
            uint32_t b[8][2];
#pragma unroll
            for (int np = 0; np < 4; np++) {      // covers n-frag pairs (2np, 2np+1)
                const int row = wn * 64 + np * 16 + (sub >> 1) * 8 + j8;
                const int col = k16 + (sub & 1) * 8;
                unsigned addr = smem_u32(bs + row * SROWH + col);
                asm volatile("ldmatrix.sync.aligned.m8n8.x4.shared.b16 {%0,%1,%2,%3}, [%4];\n"
                             : "=r"(b[2*np][0]), "=r"(b[2*np][1]),
                               "=r"(b[2*np+1][0]), "=r"(b[2*np+1][1])
                             : "r"(addr));
            }
#pragma unroll
            for (int mf = 0; mf < 4; mf++)
#pragma unroll
                for (int nf = 0; nf < 8; nf++)
                    asm volatile(
                        "mma.sync.aligned.m16n8k16.row.col.f32.f16.f16.f32 "
                        "{%0,%1,%2,%3}, {%4,%5,%6,%7}, {%8,%9}, {%0,%1,%2,%3};\n"
                        : "+f"(acc[mf][nf][0]), "+f"(acc[mf][nf][1]),
                          "+f"(acc[mf][nf][2]), "+f"(acc[mf][nf][3])
                        : "r"(a[mf][0]), "r"(a[mf][1]), "r"(a[mf][2]), "r"(a[mf][3]),
                          "r"(b[nf][0]), "r"(b[nf][1]));
        }
        cur = (cur + 1 == 3) ? 0 : cur + 1;
    }

    // Epilogue
    const float qscale = 1.44269504088896340736f * 0.03125f;   // log2e / sqrt(1024)
    const int g  = lane >> 2;
    const int tg = lane & 3;
#pragma unroll
    for (int mf = 0; mf < 4; mf++) {
#pragma unroll
        for (int nf = 0; nf < 8; nf++) {
            const int col  = bn + wn * 64 + nf * 8 + 2 * tg;
            const float b0 = bias[col], b1 = bias[col + 1];
            const int row0 = bm + wm * 64 + mf * 16 + g;
            float v00 = acc[mf][nf][0] + b0, v01 = acc[mf][nf][1] + b1;
            float v10 = acc[mf][nf][2] + b0, v11 = acc[mf][nf][3] + b1;
            if (MODE == 0) {
                const int part = col >> 10;
                const int rem  = col & 1023;
                const int h    = rem >> 6;
                const int hd0  = rem & 63;
                if (part == 0) {   // q: fold in softmax scale
                    v00 *= qscale; v01 *= qscale; v10 *= qscale; v11 *= qscale;
                }
#pragma unroll
                for (int rr = 0; rr < 2; rr++) {
                    const int row = row0 + rr * 8;
                    const int bb = row >> 11;
                    const int t  = row & (TT - 1);
                    const float vx = rr ? v10 : v00;
                    const float vy = rr ? v11 : v01;
                    if (part == 2) {
                        __half* dst = g_v + ((size_t)((bb * HH + h) * HD + hd0)) * TT + t;
                        dst[0]  = __float2half_rn(vx);
                        dst[TT] = __float2half_rn(vy);
                    } else {
                        __half* dbase = (part == 0) ? g_q : g_k;
                        *(__half2*)(dbase + ((size_t)((bb * HH + h) * TT + t)) * HD + hd0)
                            = __floats2half2_rn(vx, vy);
                    }
                }
            } else {
                *(float2*)(C + (size_t)row0 * N + col)       = make_float2(v00, v01);
                *(float2*)(C + (size_t)(row0 + 8) * N + col) = make_float2(v10, v11);
            }
        }
    }
}

// ---------------------------------------------------------------------------
// FP16 tensor-core flash attention (unchanged from R13).
// 256 threads (8 warps x 16 q-rows), 128 q/block, kv tiles 64, double-buffered.
// ---------------------------------------------------------------------------
#define QT 128

__global__ __launch_bounds__(256, 2)
void flash_fp16()
{
    extern __shared__ __half fsm[];
    __half* Ps  = fsm;                     // [128][SROWH]  Q staging, then P
    __half* Ksm = fsm + QT * SROWH;        // 2 x [64][SROWH]
    __half* Vsm = Ksm + 2 * 64 * SROWH;    // 2 x [64][SROWH]  Vt[d][c]

    const int tid  = threadIdx.x;
    const int lane = tid & 31, warp = tid >> 5;
    const int j8 = lane & 7, sub = lane >> 3;
    const int g  = lane >> 2, tg  = lane & 3;
    const int qi = blockIdx.x;
    const int bh = blockIdx.y;
    const int b = bh >> 4, h = bh & 15;

    const __half* qg = g_q + ((size_t)bh * TT + qi * QT) * HD;
    const __half* kg = g_k + (size_t)bh * TT * HD;
    const __half* vg = g_v + (size_t)bh * HD * TT;

    // Stage Q via cp.async (already scaled in GEMM epilogue)
    {
        const int r = tid >> 1;
        const int q0 = (tid & 1) * 4;
#pragma unroll
        for (int qq = 0; qq < 4; qq++) {
            const int q = q0 + qq;
            asm volatile("cp.async.cg.shared.global [%0], [%1], 16;\n"
                         :: "r"(smem_u32(Ps + r * SROWH + q * 8)),
                            "l"(qg + (size_t)r * HD + q * 8) : "memory");
        }
        asm volatile("cp.async.commit_group;\n" ::: "memory");
    }

    auto copy_kv = [&](int kb, int buf) {
        __half* kd = Ksm + buf * (64 * SROWH);
        __half* vd = Vsm + buf * (64 * SROWH);
        const int r = tid >> 2;
        const int q = tid & 3;
#pragma unroll
        for (int qq = 0; qq < 2; qq++) {
            const int c = q * 2 + qq;
            asm volatile("cp.async.cg.shared.global [%0], [%1], 16;\n"
                         :: "r"(smem_u32(kd + r * SROWH + c * 8)),
                            "l"(kg + (size_t)(kb * 64 + r) * HD + c * 8) : "memory");
            asm volatile("cp.async.cg.shared.global [%0], [%1], 16;\n"
                         :: "r"(smem_u32(vd + r * SROWH + c * 8)),
                            "l"(vg + (size_t)r * TT + kb * 64 + c * 8) : "memory");
        }
        asm volatile("cp.async.commit_group;\n" ::: "memory");
    };

    copy_kv(0, 0);
    asm volatile("cp.async.wait_group 0;\n" ::: "memory");
    __syncthreads();

    uint32_t aq[4][4];
#pragma unroll
    for (int ks = 0; ks < 4; ks++) {
        const int row = warp * 16 + (sub & 1) * 8 + j8;
        const int col = ks * 16 + (sub >> 1) * 8;
        unsigned addr = smem_u32(Ps + row * SROWH + col);
        asm volatile("ldmatrix.sync.aligned.m8n8.x4.shared.b16 {%0,%1,%2,%3}, [%4];\n"
                     : "=r"(aq[ks][0]), "=r"(aq[ks][1]), "=r"(aq[ks][2]), "=r"(aq[ks][3])
                     : "r"(addr));
    }

    float O[8][4];
    float m[2] = {NEG_INF, NEG_INF}, l[2] = {0.f, 0.f};
#pragma unroll
    for (int nf = 0; nf < 8; nf++)
#pragma unroll
        for (int e = 0; e < 4; e++) O[nf][e] = 0.f;

    const int nkv = 2 * qi + 2;
    for (int kb = 0; kb < nkv; kb++) {
        const int cur = kb & 1;
        if (kb + 1 < nkv) {
            copy_kv(kb + 1, cur ^ 1);
            asm volatile("cp.async.wait_group 1;\n" ::: "memory");
        } else {
            asm volatile("cp.async.wait_group 0;\n" ::: "memory");
        }
        __syncthreads();

        const bool active = (kb * 64 <= qi * QT + warp * 16 + 15);
        if (active) {
            const __half* Kc = Ksm + cur * (64 * SROWH);
            const __half* Vc = Vsm + cur * (64 * SROWH);

            float acc[8][4];
#pragma unroll
            for (int nf = 0; nf < 8; nf++)
#pragma unroll
                for (int e = 0; e < 4; e++) acc[nf][e] = 0.f;

#pragma unroll
            for (int ks = 0; ks < 4; ks++) {
                const int k16 = ks * 16;
                uint32_t bf[8][2];
#pragma unroll
                for (int np = 0; np < 4; np++) {
                    const int row = np * 16 + (sub >> 1) * 8 + j8;
                    const int col = k16 + (sub & 1) * 8;
                    unsigned addr = smem_u32(Kc + row * SROWH + col);
                    asm volatile("ldmatrix.sync.aligned.m8n8.x4.shared.b16 {%0,%1,%2,%3}, [%4];\n"
                                 : "=r"(bf[2*np][0]), "=r"(bf[2*np][1]),
                                   "=r"(bf[2*np+1][0]), "=r"(bf[2*np+1][1])
                                 : "r"(addr));
                }
#pragma unroll
                for (int nf = 0; nf < 8; nf++)
                    asm volatile(
                        "mma.sync.aligned.m16n8k16.row.col.f32.f16.f16.f32 "
                        "{%0,%1,%2,%3}, {%4,%5,%6,%7}, {%8,%9}, {%0,%1,%2,%3};\n"
                        : "+f"(acc[nf][0]), "+f"(acc[nf][1]),
                          "+f"(acc[nf][2]), "+f"(acc[nf][3])
                        : "r"(aq[ks][0]), "r"(aq[ks][1]), "r"(aq[ks][2]), "r"(aq[ks][3]),
                          "r"(bf[nf][0]), "r"(bf[nf][1]));
            }

            if (kb >= 2 * qi) {
                const int col0 = kb * 64 + 2 * tg;
                const int row0 = qi * QT + warp * 16 + g;
#pragma unroll
                for (int nf = 0; nf < 8; nf++)
#pragma unroll
                    for (int e = 0; e < 4; e++) {
                        const int row = row0 + (e >> 1) * 8;
                        const int col = col0 + nf * 8 + (e & 1);
                        if (col > row) acc[nf][e] = NEG_INF;
                    }
            }

#pragma unroll
            for (int rr = 0; rr < 2; rr++) {
                float rm = NEG_INF;
#pragma unroll
                for (int nf = 0; nf < 8; nf++)
                    rm = fmaxf(rm, fmaxf(acc[nf][rr*2], acc[nf][rr*2+1]));
                rm = fmaxf(rm, __shfl_xor_sync(0xffffffffu, rm, 1));
                rm = fmaxf(rm, __shfl_xor_sync(0xffffffffu, rm, 2));
                const float mo = m[rr];
                const float mn = fmaxf(mo, rm);
                const float corr = exp2f(mo - mn);
                m[rr] = mn;
                float rs = 0.f;
#pragma unroll
                for (int nf = 0; nf < 8; nf++) {
                    const float p0 = exp2f(acc[nf][rr*2]   - mn);
                    const float p1 = exp2f(acc[nf][rr*2+1] - mn);
                    acc[nf][rr*2]   = p0;
                    acc[nf][rr*2+1] = p1;
                    rs += p0 + p1;
                }
                rs += __shfl_xor_sync(0xffffffffu, rs, 1);
                rs += __shfl_xor_sync(0xffffffffu, rs, 2);
                l[rr] = l[rr] * corr + rs;
#pragma unroll
                for (int nf = 0; nf < 8; nf++) {
                    O[nf][rr*2]   *= corr;
                    O[nf][rr*2+1] *= corr;
                }
            }

            {
                const int r0 = warp * 16 + g;
#pragma unroll
                for (int nf = 0; nf < 8; nf++) {
                    const int col = nf * 8 + 2 * tg;
                    *(__half2*)(Ps + r0 * SROWH + col) =
                        __floats2half2_rn(acc[nf][0], acc[nf][1]);
                    *(__half2*)(Ps + (r0 + 8) * SROWH + col) =
                        __floats2half2_rn(acc[nf][2], acc[nf][3]);
                }
            }
            __syncwarp();

#pragma unroll
            for (int ks = 0; ks < 4; ks++) {
                const int k16 = ks * 16;
                uint32_t a[4];
                {
                    const int row = warp * 16 + (sub & 1) * 8 + j8;
                    const int col = k16 + (sub >> 1) * 8;
                    unsigned addr = smem_u32(Ps + row * SROWH + col);
                    asm volatile("ldmatrix.sync.aligned.m8n8.x4.shared.b16 {%0,%1,%2,%3}, [%4];\n"
                                 : "=r"(a[0]), "=r"(a[1]), "=r"(a[2]), "=r"(a[3])
                                 : "r"(addr));
                }
                uint32_t bf[8][2];
#pragma unroll
                for (int np = 0; np < 4; np++) {
                    const int row = np * 16 + (sub >> 1) * 8 + j8;
                    const int col = k16 + (sub & 1) * 8;
                    unsigned addr = smem_u32(Vc + row * SROWH + col);
                    asm volatile("ldmatrix.sync.aligned.m8n8.x4.shared.b16 {%0,%1,%2,%3}, [%4];\n"
                                 : "=r"(bf[2*np][0]), "=r"(bf[2*np][1]),
                                   "=r"(bf[2*np+1][0]), "=r"(bf[2*np+1][1])
                                 : "r"(addr));
                }
#pragma unroll
                for (int nf = 0; nf < 8; nf++)
                    asm volatile(
                        "mma.sync.aligned.m16n8k16.row.col.f32.f16.f16.f32 "
                        "{%0,%1,%2,%3}, {%4,%5,%6,%7}, {%8,%9}, {%0,%1,%2,%3};\n"
                        : "+f"(O[nf][0]), "+f"(O[nf][1]),
                          "+f"(O[nf][2]), "+f"(O[nf][3])
                        : "r"(a[0]), "r"(a[1]), "r"(a[2]), "r"(a[3]),
                          "r"(bf[nf][0]), "r"(bf[nf][1]));
            }
        }
        __syncthreads();
    }

#pragma unroll
    for (int rr = 0; rr < 2; rr++) {
        const float inv = 1.f / l[rr];
        const int t = qi * QT + warp * 16 + g + rr * 8;
        const size_t rowoff = (size_t)(b * TT + t) * DD + h * 64;
#pragma unroll
        for (int nf = 0; nf < 8; nf++) {
            const int d0 = nf * 8 + 2 * tg;
            *(__half2*)(g_y16 + rowoff + d0) =
                __floats2half2_rn(O[nf][rr*2] * inv, O[nf][rr*2+1] * inv);
        }
    }
}

// ---------------------------------------------------------------------------
extern "C" void kernel_launch(void* const* d_in, const int* in_sizes, int n_in,
                              void* d_out, int out_size)
{
    const float* x     = (const float*)d_in[0];
    const float* w_qkv = (const float*)d_in[1];
    const float* b_qkv = (const float*)d_in[2];
    const float* w_o   = (const float*)d_in[3];
    const float* b_o   = (const float*)d_in[4];
    float* out = (float*)d_out;

    const int gemm_smem  = 6 * HBUF * (int)sizeof(__half);                // 110592
    const int flash_smem = (QT + 4 * 64) * SROWH * (int)sizeof(__half);   // 55296
    cudaFuncSetAttribute(gemm_fp16<0>, cudaFuncAttributeMaxDynamicSharedMemorySize, gemm_smem);
    cudaFuncSetAttribute(gemm_fp16<1>, cudaFuncAttributeMaxDynamicSharedMemorySize, gemm_smem);
    cudaFuncSetAttribute(flash_fp16,   cudaFuncAttributeMaxDynamicSharedMemorySize, flash_smem);

    // Prep: convert x, transpose+convert weights
    conv_x_kernel<<<MROWS * DD / (256 * 4), 256>>>(x);
    {
        dim3 g1(3 * DD / 32, DD / 32);
        transpose_half_kernel<0><<<g1, 256>>>(w_qkv, DD, 3 * DD);
        dim3 g2(DD / 32, DD / 32);
        transpose_half_kernel<1><<<g2, 256>>>(w_o, DD, DD);
    }

    // QKV projection: [4096,1024] @ [1024,3072] -> q/k/v (fp16)
    {
        dim3 grid(3 * DD / 128, MROWS / 128);   // (24, 32)
        gemm_fp16<0><<<grid, 128, gemm_smem>>>(b_qkv, nullptr, 3 * DD);
    }
    // Flash attention (fp16 tensor cores)
    {
        dim3 grid(TT / QT, BB * HH);            // (16, 32)
        flash_fp16<<<grid, 256, flash_smem>>>();
    }
    // Output projection: [4096,1024] @ [1024,1024] + b_o -> fp32 out
    {
        dim3 grid(DD / 128, MROWS / 128);       // (8, 32)
        gemm_fp16<1><<<grid, 128, gemm_smem>>>(b_o, out, DD);
    }
}

// round 16
// speedup vs baseline: 1.2020x; 1.2020x over previous
#include <cuda_runtime.h>
#include <cuda_fp16.h>
#include <math.h>
#include <stdint.h>

#define BB 2
#define TT 2048
#define DD 1024
#define HH 16
#define HD 64
#define MROWS (BB*TT)   // 4096

// Scratch (allocation-free rule: device globals), all fp16 operands
__device__ __half g_q[BB*HH*TT*HD];    // [b][h][t][hd], pre-scaled by log2e/32
__device__ __half g_k[BB*HH*TT*HD];    // [b][h][t][hd]
__device__ __half g_v[BB*HH*TT*HD];    // [b][h][hd][t]  TRANSPOSED
__device__ __half g_x16[MROWS*DD];     // x as fp16
__device__ __half g_wqT[3*DD*DD];      // [3D][D] transposed w_qkv fp16
__device__ __half g_woT[DD*DD];        // [D][D]  transposed w_o  fp16
__device__ __half g_y16[MROWS*DD];     // attention out fp16 [b][t][h*64+hd]

#define NEG_INF __int_as_float(0xff800000)

__device__ __forceinline__ unsigned smem_u32(const void* p) {
    return (unsigned)__cvta_generic_to_shared(p);
}

// ---------------------------------------------------------------------------
// Prep: convert x to fp16
// ---------------------------------------------------------------------------
__global__ __launch_bounds__(256)
void conv_x_kernel(const float* __restrict__ x)
{
    int i = (blockIdx.x * 256 + threadIdx.x) * 4;
    float4 v = *(const float4*)(x + i);
    *(__half2*)(g_x16 + i)     = __floats2half2_rn(v.x, v.y);
    *(__half2*)(g_x16 + i + 2) = __floats2half2_rn(v.z, v.w);
}

// ---------------------------------------------------------------------------
// Prep: transpose + convert weights. dst[c][r] = fp16(src[r][c]); src RxC.
// ---------------------------------------------------------------------------
template<int WHICH>
__global__ __launch_bounds__(256)
void transpose_half_kernel(const float* __restrict__ src, int R, int C)
{
    __half* dst = (WHICH == 0) ? g_wqT : g_woT;
    __shared__ float tile[32][33];
    const int r0 = blockIdx.y * 32, c0 = blockIdx.x * 32;
    const int tx = threadIdx.x & 31, ty = threadIdx.x >> 5;
#pragma unroll
    for (int i = 0; i < 32; i += 8)
        tile[ty + i][tx] = src[(size_t)(r0 + ty + i) * C + c0 + tx];
    __syncthreads();
#pragma unroll
    for (int i = 0; i < 32; i += 8)
        dst[(size_t)(c0 + ty + i) * R + r0 + tx] = __float2half_rn(tile[tx][ty + i]);
}

// ---------------------------------------------------------------------------
// FP16 tensor-core GEMM (R13 config: 128x128 tile, 8 warps x 64x32 warp tiles,
// K-chunk 64, 3-stage cp.async, m16n8k16). fp32 accumulate.
// MODE 0: A=g_x16, Bt=g_wqT -> scatter q (scaled)/k -> [B,H,T,HD], v -> [B,H,HD,T]
// MODE 1: A=g_y16, Bt=g_woT -> fp32 C row-major (final output)
// ---------------------------------------------------------------------------
#define SROWH 72
#define HBUF (128*SROWH)   // halves per tile buffer

template<int MODE>
__global__ __launch_bounds__(256, 2)
void gemm_fp16(const float* __restrict__ bias, float* __restrict__ C, int N)
{
    extern __shared__ __half hsm[];
    __half* Asm = hsm;              // 3 buffers
    __half* Bsm = hsm + 3 * HBUF;   // 3 buffers
    const int K = DD;

    const int tid  = threadIdx.x;
    const int lane = tid & 31, warp = tid >> 5;
    const int wm = warp >> 2;       // 0..1
    const int wn = warp & 3;        // 0..3
    const int bm = blockIdx.y * 128, bn = blockIdx.x * 128;

    const __half* Aeff = (MODE == 0) ? g_x16 : g_y16;
    const __half* Bt   = (MODE == 0) ? g_wqT : g_woT;

    float acc[4][4][4];
#pragma unroll
    for (int a = 0; a < 4; a++)
#pragma unroll
        for (int b = 0; b < 4; b++)
#pragma unroll
            for (int c = 0; c < 4; c++) acc[a][b][c] = 0.f;

    auto copy_chunk = [&](int ck, int buf) {
        const __half* ag = Aeff + (size_t)bm * K + ck * 64;
        const __half* bg = Bt   + (size_t)bn * K + ck * 64;
        __half* as = Asm + buf * HBUF;
        __half* bs = Bsm + buf * HBUF;
        const int r = tid >> 1;        // 0..127
        const int q0 = (tid & 1) * 4;  // 16B-chunk index base
#pragma unroll
        for (int qq = 0; qq < 4; qq++) {
            const int q = q0 + qq;
            asm volatile("cp.async.cg.shared.global [%0], [%1], 16;\n"
                         :: "r"(smem_u32(as + r * SROWH + q * 8)),
                            "l"(ag + (size_t)r * K + q * 8) : "memory");
            asm volatile("cp.async.cg.shared.global [%0], [%1], 16;\n"
                         :: "r"(smem_u32(bs + r * SROWH + q * 8)),
                            "l"(bg + (size_t)r * K + q * 8) : "memory");
        }
        asm volatile("cp.async.commit_group;\n" ::: "memory");
    };

    copy_chunk(0, 0);
    copy_chunk(1, 1);

    const int j8  = lane & 7;
    const int sub = lane >> 3;

    int cur = 0;
    const int NCK = K / 64;   // 16
    for (int ck = 0; ck < NCK; ck++) {
        if (ck < NCK - 1) { asm volatile("cp.async.wait_group 1;\n" ::: "memory"); }
        else              { asm volatile("cp.async.wait_group 0;\n" ::: "memory"); }
        __syncthreads();
        if (ck + 2 < NCK) {
            int pf = cur + 2; if (pf >= 3) pf -= 3;
            copy_chunk(ck + 2, pf);
        }

        const __half* as = Asm + cur * HBUF;
        const __half* bs = Bsm + cur * HBUF;

#pragma unroll
        for (int ks = 0; ks < 4; ks++) {          // 4 x k16 per 64-chunk
            const int k16 = ks * 16;
            uint32_t a[4][4];
#pragma unroll
            for (int mf = 0; mf < 4; mf++) {
                const int row = wm * 64 + mf * 16 + (sub & 1) * 8 + j8;
                const int col = k16 + (sub >> 1) * 8;
                unsigned addr = smem_u32(as + row * SROWH + col);
                asm volatile("ldmatrix.sync.aligned.m8n8.x4.shared.b16 {%0,%1,%2,%3}, [%4];\n"
                             : "=r"(a[mf][0]), "=r"(a[mf][1]), "=r"(a[mf][2]), "=r"(a[mf][3])
                             : "r"(addr));
            }
            uint32_t b[4][2];
#pragma unroll
            for (int np = 0; np < 2; np++) {
                const int row = wn * 32 + np * 16 + (sub >> 1) * 8 + j8;
                const int col = k16 + (sub & 1) * 8;
                unsigned addr = smem_u32(bs + row * SROWH + col);
                asm volatile("ldmatrix.sync.aligned.m8n8.x4.shared.b16 {%0,%1,%2,%3}, [%4];\n"
                             : "=r"(b[2*np][0]), "=r"(b[2*np][1]),
                               "=r"(b[2*np+1][0]), "=r"(b[2*np+1][1])
                             : "r"(addr));
            }
#pragma unroll
            for (int mf = 0; mf < 4; mf++)
#pragma unroll
                for (int nf = 0; nf < 4; nf++)
                    asm volatile(
                        "mma.sync.aligned.m16n8k16.row.col.f32.f16.f16.f32 "
                        "{%0,%1,%2,%3}, {%4,%5,%6,%7}, {%8,%9}, {%0,%1,%2,%3};\n"
                        : "+f"(acc[mf][nf][0]), "+f"(acc[mf][nf][1]),
                          "+f"(acc[mf][nf][2]), "+f"(acc[mf][nf][3])
                        : "r"(a[mf][0]), "r"(a[mf][1]), "r"(a[mf][2]), "r"(a[mf][3]),
                          "r"(b[nf][0]), "r"(b[nf][1]));
        }
        cur = (cur + 1 == 3) ? 0 : cur + 1;
    }

    // Epilogue
    const float qscale = 1.44269504088896340736f * 0.03125f;   // log2e / sqrt(1024)
    const int g  = lane >> 2;
    const int tg = lane & 3;
#pragma unroll
    for (int mf = 0; mf < 4; mf++) {
#pragma unroll
        for (int nf = 0; nf < 4; nf++) {
            const int col  = bn + wn * 32 + nf * 8 + 2 * tg;
            const float b0 = bias[col], b1 = bias[col + 1];
            const int row0 = bm + wm * 64 + mf * 16 + g;
            float v00 = acc[mf][nf][0] + b0, v01 = acc[mf][nf][1] + b1;
            float v10 = acc[mf][nf][2] + b0, v11 = acc[mf][nf][3] + b1;
            if (MODE == 0) {
                const int part = col >> 10;
                const int rem  = col & 1023;
                const int h    = rem >> 6;
                const int hd0  = rem & 63;
                if (part == 0) {
                    v00 *= qscale; v01 *= qscale; v10 *= qscale; v11 *= qscale;
                }
#pragma unroll
                for (int rr = 0; rr < 2; rr++) {
                    const int row = row0 + rr * 8;
                    const int bb = row >> 11;
                    const int t  = row & (TT - 1);
                    const float vx = rr ? v10 : v00;
                    const float vy = rr ? v11 : v01;
                    if (part == 2) {
                        __half* dst = g_v + ((size_t)((bb * HH + h) * HD + hd0)) * TT + t;
                        dst[0]  = __float2half_rn(vx);
                        dst[TT] = __float2half_rn(vy);
                    } else {
                        __half* dbase = (part == 0) ? g_q : g_k;
                        *(__half2*)(dbase + ((size_t)((bb * HH + h) * TT + t)) * HD + hd0)
                            = __floats2half2_rn(vx, vy);
                    }
                }
            } else {
                *(float2*)(C + (size_t)row0 * N + col)       = make_float2(v00, v01);
                *(float2*)(C + (size_t)(row0 + 8) * N + col) = make_float2(v10, v11);
            }
        }
    }
}

// ---------------------------------------------------------------------------
// FP16 tensor-core flash attention, balanced two-tile blocks.
// Block bx handles query tiles bx and 15-bx (work = 34 kv-tiles, uniform).
// Grid (8, 32) = 256 CTAs = one fully-resident balanced wave at 2 CTA/SM.
// ---------------------------------------------------------------------------
#define QT 128

__global__ __launch_bounds__(256, 2)
void flash_fp16()
{
    extern __shared__ __half fsm[];
    __half* Ps  = fsm;                     // [128][SROWH]  Q staging, then P
    __half* Ksm = fsm + QT * SROWH;        // 2 x [64][SROWH]
    __half* Vsm = Ksm + 2 * 64 * SROWH;    // 2 x [64][SROWH]  Vt[d][c]

    const int tid  = threadIdx.x;
    const int lane = tid & 31, warp = tid >> 5;
    const int j8 = lane & 7, sub = lane >> 3;
    const int g  = lane >> 2, tg  = lane & 3;
    const int bh = blockIdx.y;
    const int b = bh >> 4, h = bh & 15;

    const __half* kg = g_k + (size_t)bh * TT * HD;
    const __half* vg = g_v + (size_t)bh * HD * TT;

    auto copy_kv = [&](int kb, int buf) {
        __half* kd = Ksm + buf * (64 * SROWH);
        __half* vd = Vsm + buf * (64 * SROWH);
        const int r = tid >> 2;
        const int q = tid & 3;
#pragma unroll
        for (int qq = 0; qq < 2; qq++) {
            const int c = q * 2 + qq;
            asm volatile("cp.async.cg.shared.global [%0], [%1], 16;\n"
                         :: "r"(smem_u32(kd + r * SROWH + c * 8)),
                            "l"(kg + (size_t)(kb * 64 + r) * HD + c * 8) : "memory");
            asm volatile("cp.async.cg.shared.global [%0], [%1], 16;\n"
                         :: "r"(smem_u32(vd + r * SROWH + c * 8)),
                            "l"(vg + (size_t)r * TT + kb * 64 + c * 8) : "memory");
        }
        asm volatile("cp.async.commit_group;\n" ::: "memory");
    };

#pragma unroll 1
    for (int pass = 0; pass < 2; pass++) {
        const int qi = pass ? (15 - (int)blockIdx.x) : (int)blockIdx.x;
        const __half* qg = g_q + ((size_t)bh * TT + qi * QT) * HD;

        // Stage Q via cp.async (already scaled in GEMM epilogue)
        {
            const int r = tid >> 1;
            const int q0 = (tid & 1) * 4;
#pragma unroll
            for (int qq = 0; qq < 4; qq++) {
                const int q = q0 + qq;
                asm volatile("cp.async.cg.shared.global [%0], [%1], 16;\n"
                             :: "r"(smem_u32(Ps + r * SROWH + q * 8)),
                                "l"(qg + (size_t)r * HD + q * 8) : "memory");
            }
            asm volatile("cp.async.commit_group;\n" ::: "memory");
        }

        copy_kv(0, 0);
        asm volatile("cp.async.wait_group 0;\n" ::: "memory");
        __syncthreads();

        // Q A-fragments (own-warp rows), then Ps is free for P
        uint32_t aq[4][4];
#pragma unroll
        for (int ks = 0; ks < 4; ks++) {
            const int row = warp * 16 + (sub & 1) * 8 + j8;
            const int col = ks * 16 + (sub >> 1) * 8;
            unsigned addr = smem_u32(Ps + row * SROWH + col);
            asm volatile("ldmatrix.sync.aligned.m8n8.x4.shared.b16 {%0,%1,%2,%3}, [%4];\n"
                         : "=r"(aq[ks][0]), "=r"(aq[ks][1]), "=r"(aq[ks][2]), "=r"(aq[ks][3])
                         : "r"(addr));
        }

        float O[8][4];
        float m[2] = {NEG_INF, NEG_INF}, l[2] = {0.f, 0.f};
#pragma unroll
        for (int nf = 0; nf < 8; nf++)
#pragma unroll
            for (int e = 0; e < 4; e++) O[nf][e] = 0.f;

        const int nkv = 2 * qi + 2;
        for (int kb = 0; kb < nkv; kb++) {
            const int cur = kb & 1;
            if (kb + 1 < nkv) {
                copy_kv(kb + 1, cur ^ 1);
                asm volatile("cp.async.wait_group 1;\n" ::: "memory");
            } else {
                asm volatile("cp.async.wait_group 0;\n" ::: "memory");
            }
            __syncthreads();

            const bool active = (kb * 64 <= qi * QT + warp * 16 + 15);
            if (active) {
                const __half* Kc = Ksm + cur * (64 * SROWH);
                const __half* Vc = Vsm + cur * (64 * SROWH);

                // ---- S = Q K^T ----
                float acc[8][4];
#pragma unroll
                for (int nf = 0; nf < 8; nf++)
#pragma unroll
                    for (int e = 0; e < 4; e++) acc[nf][e] = 0.f;

#pragma unroll
                for (int ks = 0; ks < 4; ks++) {
                    const int k16 = ks * 16;
                    uint32_t bf[8][2];
#pragma unroll
                    for (int np = 0; np < 4; np++) {
                        const int row = np * 16 + (sub >> 1) * 8 + j8;
                        const int col = k16 + (sub & 1) * 8;
                        unsigned addr = smem_u32(Kc + row * SROWH + col);
                        asm volatile("ldmatrix.sync.aligned.m8n8.x4.shared.b16 {%0,%1,%2,%3}, [%4];\n"
                                     : "=r"(bf[2*np][0]), "=r"(bf[2*np][1]),
                                       "=r"(bf[2*np+1][0]), "=r"(bf[2*np+1][1])
                                     : "r"(addr));
                    }
#pragma unroll
                    for (int nf = 0; nf < 8; nf++)
                        asm volatile(
                            "mma.sync.aligned.m16n8k16.row.col.f32.f16.f16.f32 "
                            "{%0,%1,%2,%3}, {%4,%5,%6,%7}, {%8,%9}, {%0,%1,%2,%3};\n"
                            : "+f"(acc[nf][0]), "+f"(acc[nf][1]),
                              "+f"(acc[nf][2]), "+f"(acc[nf][3])
                            : "r"(aq[ks][0]), "r"(aq[ks][1]), "r"(aq[ks][2]), "r"(aq[ks][3]),
                              "r"(bf[nf][0]), "r"(bf[nf][1]));
                }

                // ---- causal mask ----
                if (kb >= 2 * qi) {
                    const int col0 = kb * 64 + 2 * tg;
                    const int row0 = qi * QT + warp * 16 + g;
#pragma unroll
                    for (int nf = 0; nf < 8; nf++)
#pragma unroll
                        for (int e = 0; e < 4; e++) {
                            const int row = row0 + (e >> 1) * 8;
                            const int col = col0 + nf * 8 + (e & 1);
                            if (col > row) acc[nf][e] = NEG_INF;
                        }
                }

                // ---- online softmax (exp2 domain) ----
#pragma unroll
                for (int rr = 0; rr < 2; rr++) {
                    float rm = NEG_INF;
#pragma unroll
                    for (int nf = 0; nf < 8; nf++)
                        rm = fmaxf(rm, fmaxf(acc[nf][rr*2], acc[nf][rr*2+1]));
                    rm = fmaxf(rm, __shfl_xor_sync(0xffffffffu, rm, 1));
                    rm = fmaxf(rm, __shfl_xor_sync(0xffffffffu, rm, 2));
                    const float mo = m[rr];
                    const float mn = fmaxf(mo, rm);
                    const float corr = exp2f(mo - mn);
                    m[rr] = mn;
                    float rs = 0.f;
#pragma unroll
                    for (int nf = 0; nf < 8; nf++) {
                        const float p0 = exp2f(acc[nf][rr*2]   - mn);
                        const float p1 = exp2f(acc[nf][rr*2+1] - mn);
                        acc[nf][rr*2]   = p0;
                        acc[nf][rr*2+1] = p1;
                        rs += p0 + p1;
                    }
                    rs += __shfl_xor_sync(0xffffffffu, rs, 1);
                    rs += __shfl_xor_sync(0xffffffffu, rs, 2);
                    l[rr] = l[rr] * corr + rs;
#pragma unroll
                    for (int nf = 0; nf < 8; nf++) {
                        O[nf][rr*2]   *= corr;
                        O[nf][rr*2+1] *= corr;
                    }
                }

                // ---- write P as fp16 (own-warp rows) ----
                {
                    const int r0 = warp * 16 + g;
#pragma unroll
                    for (int nf = 0; nf < 8; nf++) {
                        const int col = nf * 8 + 2 * tg;
                        *(__half2*)(Ps + r0 * SROWH + col) =
                            __floats2half2_rn(acc[nf][0], acc[nf][1]);
                        *(__half2*)(Ps + (r0 + 8) * SROWH + col) =
                            __floats2half2_rn(acc[nf][2], acc[nf][3]);
                    }
                }
                __syncwarp();

                // ---- O += P @ V ----
#pragma unroll
                for (int ks = 0; ks < 4; ks++) {
                    const int k16 = ks * 16;
                    uint32_t a[4];
                    {
                        const int row = warp * 16 + (sub & 1) * 8 + j8;
                        const int col = k16 + (sub >> 1) * 8;
                        unsigned addr = smem_u32(Ps + row * SROWH + col);
                        asm volatile("ldmatrix.sync.aligned.m8n8.x4.shared.b16 {%0,%1,%2,%3}, [%4];\n"
                                     : "=r"(a[0]), "=r"(a[1]), "=r"(a[2]), "=r"(a[3])
                                     : "r"(addr));
                    }
                    uint32_t bf[8][2];
#pragma unroll
                    for (int np = 0; np < 4; np++) {
                        const int row = np * 16 + (sub >> 1) * 8 + j8;
                        const int col = k16 + (sub & 1) * 8;
                        unsigned addr = smem_u32(Vc + row * SROWH + col);
                        asm volatile("ldmatrix.sync.aligned.m8n8.x4.shared.b16 {%0,%1,%2,%3}, [%4];\n"
                                     : "=r"(bf[2*np][0]), "=r"(bf[2*np][1]),
                                       "=r"(bf[2*np+1][0]), "=r"(bf[2*np+1][1])
                                     : "r"(addr));
                    }
#pragma unroll
                    for (int nf = 0; nf < 8; nf++)
                        asm volatile(
                            "mma.sync.aligned.m16n8k16.row.col.f32.f16.f16.f32 "
                            "{%0,%1,%2,%3}, {%4,%5,%6,%7}, {%8,%9}, {%0,%1,%2,%3};\n"
                            : "+f"(O[nf][0]), "+f"(O[nf][1]),
                              "+f"(O[nf][2]), "+f"(O[nf][3])
                            : "r"(a[0]), "r"(a[1]), "r"(a[2]), "r"(a[3]),
                              "r"(bf[nf][0]), "r"(bf[nf][1]));
                }
            }
            __syncthreads();
        }

        // ---- epilogue: normalize, fp16, write g_y16 [b][t][h*64+d] ----
#pragma unroll
        for (int rr = 0; rr < 2; rr++) {
            const float inv = 1.f / l[rr];
            const int t = qi * QT + warp * 16 + g + rr * 8;
            const size_t rowoff = (size_t)(b * TT + t) * DD + h * 64;
#pragma unroll
            for (int nf = 0; nf < 8; nf++) {
                const int d0 = nf * 8 + 2 * tg;
                *(__half2*)(g_y16 + rowoff + d0) =
                    __floats2half2_rn(O[nf][rr*2] * inv, O[nf][rr*2+1] * inv);
            }
        }
    }
}

// ---------------------------------------------------------------------------
extern "C" void kernel_launch(void* const* d_in, const int* in_sizes, int n_in,
                              void* d_out, int out_size)
{
    const float* x     = (const float*)d_in[0];
    const float* w_qkv = (const float*)d_in[1];
    const float* b_qkv = (const float*)d_in[2];
    const float* w_o   = (const float*)d_in[3];
    const float* b_o   = (const float*)d_in[4];
    float* out = (float*)d_out;

    const int gemm_smem  = 6 * HBUF * (int)sizeof(__half);                // 110592
    const int flash_smem = (QT + 4 * 64) * SROWH * (int)sizeof(__half);   // 55296
    cudaFuncSetAttribute(gemm_fp16<0>, cudaFuncAttributeMaxDynamicSharedMemorySize, gemm_smem);
    cudaFuncSetAttribute(gemm_fp16<1>, cudaFuncAttributeMaxDynamicSharedMemorySize, gemm_smem);
    cudaFuncSetAttribute(flash_fp16,   cudaFuncAttributeMaxDynamicSharedMemorySize, flash_smem);

    // Prep: convert x, transpose+convert weights
    conv_x_kernel<<<MROWS * DD / (256 * 4), 256>>>(x);
    {
        dim3 g1(3 * DD / 32, DD / 32);
        transpose_half_kernel<0><<<g1, 256>>>(w_qkv, DD, 3 * DD);
        dim3 g2(DD / 32, DD / 32);
        transpose_half_kernel<1><<<g2, 256>>>(w_o, DD, DD);
    }

    // QKV projection: [4096,1024] @ [1024,3072] -> q/k/v (fp16)
    {
        dim3 grid(3 * DD / 128, MROWS / 128);   // (24, 32)
        gemm_fp16<0><<<grid, 256, gemm_smem>>>(b_qkv, nullptr, 3 * DD);
    }
    // Flash attention (fp16 tensor cores, balanced two-tile blocks)
    {
        dim3 grid(8, BB * HH);                  // (8, 32) = 256 balanced CTAs
        flash_fp16<<<grid, 256, flash_smem>>>();
    }
    // Output projection: [4096,1024] @ [1024,1024] + b_o -> fp32 out
    {
        dim3 grid(DD / 128, MROWS / 128);       // (8, 32)
        gemm_fp16<1><<<grid, 256, gemm_smem>>>(b_o, out, DD);
    }
}

// round 17
// speedup vs baseline: 1.3815x; 1.1494x over previous
#include <cuda_runtime.h>
#include <cuda_fp16.h>
#include <math.h>
#include <stdint.h>

#define BB 2
#define TT 2048
#define DD 1024
#define HH 16
#define HD 64
#define MROWS (BB*TT)   // 4096

// Scratch (allocation-free rule: device globals), all fp16 operands
__device__ __half g_q[BB*HH*TT*HD];    // [b][h][t][hd], pre-scaled by log2e/32
__device__ __half g_k[BB*HH*TT*HD];    // [b][h][t][hd]
__device__ __half g_v[BB*HH*TT*HD];    // [b][h][hd][t]  TRANSPOSED
__device__ __half g_x16[MROWS*DD];     // x as fp16
__device__ __half g_wqT[3*DD*DD];      // [3D][D] transposed w_qkv fp16
__device__ __half g_woT[DD*DD];        // [D][D]  transposed w_o  fp16
__device__ __half g_y16[MROWS*DD];     // attention out fp16 [b][t][h*64+hd]

#define NEG_INF __int_as_float(0xff800000)

__device__ __forceinline__ unsigned smem_u32(const void* p) {
    return (unsigned)__cvta_generic_to_shared(p);
}

// ---------------------------------------------------------------------------
// Prep: convert x to fp16
// ---------------------------------------------------------------------------
__global__ __launch_bounds__(256)
void conv_x_kernel(const float* __restrict__ x)
{
    int i = (blockIdx.x * 256 + threadIdx.x) * 4;
    float4 v = *(const float4*)(x + i);
    *(__half2*)(g_x16 + i)     = __floats2half2_rn(v.x, v.y);
    *(__half2*)(g_x16 + i + 2) = __floats2half2_rn(v.z, v.w);
}

// ---------------------------------------------------------------------------
// Prep: transpose + convert weights. dst[c][r] = fp16(src[r][c]); src RxC.
// ---------------------------------------------------------------------------
template<int WHICH>
__global__ __launch_bounds__(256)
void transpose_half_kernel(const float* __restrict__ src, int R, int C)
{
    __half* dst = (WHICH == 0) ? g_wqT : g_woT;
    __shared__ float tile[32][33];
    const int r0 = blockIdx.y * 32, c0 = blockIdx.x * 32;
    const int tx = threadIdx.x & 31, ty = threadIdx.x >> 5;
#pragma unroll
    for (int i = 0; i < 32; i += 8)
        tile[ty + i][tx] = src[(size_t)(r0 + ty + i) * C + c0 + tx];
    __syncthreads();
#pragma unroll
    for (int i = 0; i < 32; i += 8)
        dst[(size_t)(c0 + ty + i) * R + r0 + tx] = __float2half_rn(tile[tx][ty + i]);
}

// ---------------------------------------------------------------------------
// FP16 tensor-core GEMM: 128x128 tile, 512 threads (16 warps x 32x32 warp
// tiles), K-chunk 64, 3-stage cp.async, m16n8k16, fp32 accumulate.
// 64-reg bound -> 2 CTA/SM -> 32 warps/SM (2x latency hiding vs R16).
// MODE 0: A=g_x16, Bt=g_wqT -> scatter q (scaled)/k -> [B,H,T,HD], v -> [B,H,HD,T]
// MODE 1: A=g_y16, Bt=g_woT -> fp32 C row-major (final output)
// ---------------------------------------------------------------------------
#define SROWH 72
#define HBUF (128*SROWH)   // halves per tile buffer

template<int MODE>
__global__ __launch_bounds__(512, 2)
void gemm_fp16(const float* __restrict__ bias, float* __restrict__ C, int N)
{
    extern __shared__ __half hsm[];
    __half* Asm = hsm;              // 3 buffers
    __half* Bsm = hsm + 3 * HBUF;   // 3 buffers
    const int K = DD;

    const int tid  = threadIdx.x;
    const int lane = tid & 31, warp = tid >> 5;   // 16 warps
    const int wm = warp >> 2;       // 0..3
    const int wn = warp & 3;        // 0..3
    const int bm = blockIdx.y * 128, bn = blockIdx.x * 128;

    const __half* Aeff = (MODE == 0) ? g_x16 : g_y16;
    const __half* Bt   = (MODE == 0) ? g_wqT : g_woT;

    float acc[2][4][4];
#pragma unroll
    for (int a = 0; a < 2; a++)
#pragma unroll
        for (int b = 0; b < 4; b++)
#pragma unroll
            for (int c = 0; c < 4; c++) acc[a][b][c] = 0.f;

    auto copy_chunk = [&](int ck, int buf) {
        const __half* ag = Aeff + (size_t)bm * K + ck * 64;
        const __half* bg = Bt   + (size_t)bn * K + ck * 64;
        __half* as = Asm + buf * HBUF;
        __half* bs = Bsm + buf * HBUF;
        const int r = tid >> 2;          // 0..127
        const int q0 = (tid & 3) * 2;    // 16B-chunk base (0,2,4,6)
#pragma unroll
        for (int qq = 0; qq < 2; qq++) {
            const int q = q0 + qq;       // 0..7
            asm volatile("cp.async.cg.shared.global [%0], [%1], 16;\n"
                         :: "r"(smem_u32(as + r * SROWH + q * 8)),
                            "l"(ag + (size_t)r * K + q * 8) : "memory");
            asm volatile("cp.async.cg.shared.global [%0], [%1], 16;\n"
                         :: "r"(smem_u32(bs + r * SROWH + q * 8)),
                            "l"(bg + (size_t)r * K + q * 8) : "memory");
        }
        asm volatile("cp.async.commit_group;\n" ::: "memory");
    };

    copy_chunk(0, 0);
    copy_chunk(1, 1);

    const int j8  = lane & 7;
    const int sub = lane >> 3;

    int cur = 0;
    const int NCK = K / 64;   // 16
    for (int ck = 0; ck < NCK; ck++) {
        if (ck < NCK - 1) { asm volatile("cp.async.wait_group 1;\n" ::: "memory"); }
        else              { asm volatile("cp.async.wait_group 0;\n" ::: "memory"); }
        __syncthreads();
        if (ck + 2 < NCK) {
            int pf = cur + 2; if (pf >= 3) pf -= 3;
            copy_chunk(ck + 2, pf);
        }

        const __half* as = Asm + cur * HBUF;
        const __half* bs = Bsm + cur * HBUF;

#pragma unroll
        for (int ks = 0; ks < 4; ks++) {          // 4 x k16 per 64-chunk
            const int k16 = ks * 16;
            uint32_t a[2][4];
#pragma unroll
            for (int mf = 0; mf < 2; mf++) {
                const int row = wm * 32 + mf * 16 + (sub & 1) * 8 + j8;
                const int col = k16 + (sub >> 1) * 8;
                unsigned addr = smem_u32(as + row * SROWH + col);
                asm volatile("ldmatrix.sync.aligned.m8n8.x4.shared.b16 {%0,%1,%2,%3}, [%4];\n"
                             : "=r"(a[mf][0]), "=r"(a[mf][1]), "=r"(a[mf][2]), "=r"(a[mf][3])
                             : "r"(addr));
            }
            uint32_t b[4][2];
#pragma unroll
            for (int np = 0; np < 2; np++) {      // covers n-frag pairs (2np, 2np+1)
                const int row = wn * 32 + np * 16 + (sub >> 1) * 8 + j8;
                const int col = k16 + (sub & 1) * 8;
                unsigned addr = smem_u32(bs + row * SROWH + col);
                asm volatile("ldmatrix.sync.aligned.m8n8.x4.shared.b16 {%0,%1,%2,%3}, [%4];\n"
                             : "=r"(b[2*np][0]), "=r"(b[2*np][1]),
                               "=r"(b[2*np+1][0]), "=r"(b[2*np+1][1])
                             : "r"(addr));
            }
#pragma unroll
            for (int mf = 0; mf < 2; mf++)
#pragma unroll
                for (int nf = 0; nf < 4; nf++)
                    asm volatile(
                        "mma.sync.aligned.m16n8k16.row.col.f32.f16.f16.f32 "
                        "{%0,%1,%2,%3}, {%4,%5,%6,%7}, {%8,%9}, {%0,%1,%2,%3};\n"
                        : "+f"(acc[mf][nf][0]), "+f"(acc[mf][nf][1]),
                          "+f"(acc[mf][nf][2]), "+f"(acc[mf][nf][3])
                        : "r"(a[mf][0]), "r"(a[mf][1]), "r"(a[mf][2]), "r"(a[mf][3]),
                          "r"(b[nf][0]), "r"(b[nf][1]));
        }
        cur = (cur + 1 == 3) ? 0 : cur + 1;
    }

    // Epilogue
    const float qscale = 1.44269504088896340736f * 0.03125f;   // log2e / sqrt(1024)
    const int g  = lane >> 2;
    const int tg = lane & 3;
#pragma unroll
    for (int mf = 0; mf < 2; mf++) {
#pragma unroll
        for (int nf = 0; nf < 4; nf++) {
            const int col  = bn + wn * 32 + nf * 8 + 2 * tg;
            const float b0 = bias[col], b1 = bias[col + 1];
            const int row0 = bm + wm * 32 + mf * 16 + g;
            float v00 = acc[mf][nf][0] + b0, v01 = acc[mf][nf][1] + b1;
            float v10 = acc[mf][nf][2] + b0, v11 = acc[mf][nf][3] + b1;
            if (MODE == 0) {
                const int part = col >> 10;
                const int rem  = col & 1023;
                const int h    = rem >> 6;
                const int hd0  = rem & 63;
                if (part == 0) {
                    v00 *= qscale; v01 *= qscale; v10 *= qscale; v11 *= qscale;
                }
#pragma unroll
                for (int rr = 0; rr < 2; rr++) {
                    const int row = row0 + rr * 8;
                    const int bb = row >> 11;
                    const int t  = row & (TT - 1);
                    const float vx = rr ? v10 : v00;
                    const float vy = rr ? v11 : v01;
                    if (part == 2) {
                        __half* dst = g_v + ((size_t)((bb * HH + h) * HD + hd0)) * TT + t;
                        dst[0]  = __float2half_rn(vx);
                        dst[TT] = __float2half_rn(vy);
                    } else {
                        __half* dbase = (part == 0) ? g_q : g_k;
                        *(__half2*)(dbase + ((size_t)((bb * HH + h) * TT + t)) * HD + hd0)
                            = __floats2half2_rn(vx, vy);
                    }
                }
            } else {
                *(float2*)(C + (size_t)row0 * N + col)       = make_float2(v00, v01);
                *(float2*)(C + (size_t)(row0 + 8) * N + col) = make_float2(v10, v11);
            }
        }
    }
}

// ---------------------------------------------------------------------------
// FP16 tensor-core flash attention, balanced two-tile blocks (R16 winner).
// Block bx handles query tiles bx and 15-bx (work = 34 kv-tiles, uniform).
// ---------------------------------------------------------------------------
#define QT 128

__global__ __launch_bounds__(256, 2)
void flash_fp16()
{
    extern __shared__ __half fsm[];
    __half* Ps  = fsm;                     // [128][SROWH]  Q staging, then P
    __half* Ksm = fsm + QT * SROWH;        // 2 x [64][SROWH]
    __half* Vsm = Ksm + 2 * 64 * SROWH;    // 2 x [64][SROWH]  Vt[d][c]

    const int tid  = threadIdx.x;
    const int lane = tid & 31, warp = tid >> 5;
    const int j8 = lane & 7, sub = lane >> 3;
    const int g  = lane >> 2, tg  = lane & 3;
    const int bh = blockIdx.y;
    const int b = bh >> 4, h = bh & 15;

    const __half* kg = g_k + (size_t)bh * TT * HD;
    const __half* vg = g_v + (size_t)bh * HD * TT;

    auto copy_kv = [&](int kb, int buf) {
        __half* kd = Ksm + buf * (64 * SROWH);
        __half* vd = Vsm + buf * (64 * SROWH);
        const int r = tid >> 2;
        const int q = tid & 3;
#pragma unroll
        for (int qq = 0; qq < 2; qq++) {
            const int c = q * 2 + qq;
            asm volatile("cp.async.cg.shared.global [%0], [%1], 16;\n"
                         :: "r"(smem_u32(kd + r * SROWH + c * 8)),
                            "l"(kg + (size_t)(kb * 64 + r) * HD + c * 8) : "memory");
            asm volatile("cp.async.cg.shared.global [%0], [%1], 16;\n"
                         :: "r"(smem_u32(vd + r * SROWH + c * 8)),
                            "l"(vg + (size_t)r * TT + kb * 64 + c * 8) : "memory");
        }
        asm volatile("cp.async.commit_group;\n" ::: "memory");
    };

#pragma unroll 1
    for (int pass = 0; pass < 2; pass++) {
        const int qi = pass ? (15 - (int)blockIdx.x) : (int)blockIdx.x;
        const __half* qg = g_q + ((size_t)bh * TT + qi * QT) * HD;

        // Stage Q via cp.async (already scaled in GEMM epilogue)
        {
            const int r = tid >> 1;
            const int q0 = (tid & 1) * 4;
#pragma unroll
            for (int qq = 0; qq < 4; qq++) {
                const int q = q0 + qq;
                asm volatile("cp.async.cg.shared.global [%0], [%1], 16;\n"
                             :: "r"(smem_u32(Ps + r * SROWH + q * 8)),
                                "l"(qg + (size_t)r * HD + q * 8) : "memory");
            }
            asm volatile("cp.async.commit_group;\n" ::: "memory");
        }

        copy_kv(0, 0);
        asm volatile("cp.async.wait_group 0;\n" ::: "memory");
        __syncthreads();

        // Q A-fragments (own-warp rows), then Ps is free for P
        uint32_t aq[4][4];
#pragma unroll
        for (int ks = 0; ks < 4; ks++) {
            const int row = warp * 16 + (sub & 1) * 8 + j8;
            const int col = ks * 16 + (sub >> 1) * 8;
            unsigned addr = smem_u32(Ps + row * SROWH + col);
            asm volatile("ldmatrix.sync.aligned.m8n8.x4.shared.b16 {%0,%1,%2,%3}, [%4];\n"
                         : "=r"(aq[ks][0]), "=r"(aq[ks][1]), "=r"(aq[ks][2]), "=r"(aq[ks][3])
                         : "r"(addr));
        }

        float O[8][4];
        float m[2] = {NEG_INF, NEG_INF}, l[2] = {0.f, 0.f};
#pragma unroll
        for (int nf = 0; nf < 8; nf++)
#pragma unroll
            for (int e = 0; e < 4; e++) O[nf][e] = 0.f;

        const int nkv = 2 * qi + 2;
        for (int kb = 0; kb < nkv; kb++) {
            const int cur = kb & 1;
            if (kb + 1 < nkv) {
                copy_kv(kb + 1, cur ^ 1);
                asm volatile("cp.async.wait_group 1;\n" ::: "memory");
            } else {
                asm volatile("cp.async.wait_group 0;\n" ::: "memory");
            }
            __syncthreads();

            const bool active = (kb * 64 <= qi * QT + warp * 16 + 15);
            if (active) {
                const __half* Kc = Ksm + cur * (64 * SROWH);
                const __half* Vc = Vsm + cur * (64 * SROWH);

                // ---- S = Q K^T ----
                float acc[8][4];
#pragma unroll
                for (int nf = 0; nf < 8; nf++)
#pragma unroll
                    for (int e = 0; e < 4; e++) acc[nf][e] = 0.f;

#pragma unroll
                for (int ks = 0; ks < 4; ks++) {
                    const int k16 = ks * 16;
                    uint32_t bf[8][2];
#pragma unroll
                    for (int np = 0; np < 4; np++) {
                        const int row = np * 16 + (sub >> 1) * 8 + j8;
                        const int col = k16 + (sub & 1) * 8;
                        unsigned addr = smem_u32(Kc + row * SROWH + col);
                        asm volatile("ldmatrix.sync.aligned.m8n8.x4.shared.b16 {%0,%1,%2,%3}, [%4];\n"
                                     : "=r"(bf[2*np][0]), "=r"(bf[2*np][1]),
                                       "=r"(bf[2*np+1][0]), "=r"(bf[2*np+1][1])
                                     : "r"(addr));
                    }
#pragma unroll
                    for (int nf = 0; nf < 8; nf++)
                        asm volatile(
                            "mma.sync.aligned.m16n8k16.row.col.f32.f16.f16.f32 "
                            "{%0,%1,%2,%3}, {%4,%5,%6,%7}, {%8,%9}, {%0,%1,%2,%3};\n"
                            : "+f"(acc[nf][0]), "+f"(acc[nf][1]),
                              "+f"(acc[nf][2]), "+f"(acc[nf][3])
                            : "r"(aq[ks][0]), "r"(aq[ks][1]), "r"(aq[ks][2]), "r"(aq[ks][3]),
                              "r"(bf[nf][0]), "r"(bf[nf][1]));
                }

                // ---- causal mask ----
                if (kb >= 2 * qi) {
                    const int col0 = kb * 64 + 2 * tg;
                    const int row0 = qi * QT + warp * 16 + g;
#pragma unroll
                    for (int nf = 0; nf < 8; nf++)
#pragma unroll
                        for (int e = 0; e < 4; e++) {
                            const int row = row0 + (e >> 1) * 8;
                            const int col = col0 + nf * 8 + (e & 1);
                            if (col > row) acc[nf][e] = NEG_INF;
                        }
                }

                // ---- online softmax (exp2 domain) ----
#pragma unroll
                for (int rr = 0; rr < 2; rr++) {
                    float rm = NEG_INF;
#pragma unroll
                    for (int nf = 0; nf < 8; nf++)
                        rm = fmaxf(rm, fmaxf(acc[nf][rr*2], acc[nf][rr*2+1]));
                    rm = fmaxf(rm, __shfl_xor_sync(0xffffffffu, rm, 1));
                    rm = fmaxf(rm, __shfl_xor_sync(0xffffffffu, rm, 2));
                    const float mo = m[rr];
                    const float mn = fmaxf(mo, rm);
                    const float corr = exp2f(mo - mn);
                    m[rr] = mn;
                    float rs = 0.f;
#pragma unroll
                    for (int nf = 0; nf < 8; nf++) {
                        const float p0 = exp2f(acc[nf][rr*2]   - mn);
                        const float p1 = exp2f(acc[nf][rr*2+1] - mn);
                        acc[nf][rr*2]   = p0;
                        acc[nf][rr*2+1] = p1;
                        rs += p0 + p1;
                    }
                    rs += __shfl_xor_sync(0xffffffffu, rs, 1);
                    rs += __shfl_xor_sync(0xffffffffu, rs, 2);
                    l[rr] = l[rr] * corr + rs;
#pragma unroll
                    for (int nf = 0; nf < 8; nf++) {
                        O[nf][rr*2]   *= corr;
                        O[nf][rr*2+1] *= corr;
                    }
                }

                // ---- write P as fp16 (own-warp rows) ----
                {
                    const int r0 = warp * 16 + g;
#pragma unroll
                    for (int nf = 0; nf < 8; nf++) {
                        const int col = nf * 8 + 2 * tg;
                        *(__half2*)(Ps + r0 * SROWH + col) =
                            __floats2half2_rn(acc[nf][0], acc[nf][1]);
                        *(__half2*)(Ps + (r0 + 8) * SROWH + col) =
                            __floats2half2_rn(acc[nf][2], acc[nf][3]);
                    }
                }
                __syncwarp();

                // ---- O += P @ V ----
#pragma unroll
                for (int ks = 0; ks < 4; ks++) {
                    const int k16 = ks * 16;
                    uint32_t a[4];
                    {
                        const int row = warp * 16 + (sub & 1) * 8 + j8;
                        const int col = k16 + (sub >> 1) * 8;
                        unsigned addr = smem_u32(Ps + row * SROWH + col);
                        asm volatile("ldmatrix.sync.aligned.m8n8.x4.shared.b16 {%0,%1,%2,%3}, [%4];\n"
                                     : "=r"(a[0]), "=r"(a[1]), "=r"(a[2]), "=r"(a[3])
                                     : "r"(addr));
                    }
                    uint32_t bf[8][2];
#pragma unroll
                    for (int np = 0; np < 4; np++) {
                        const int row = np * 16 + (sub >> 1) * 8 + j8;
                        const int col = k16 + (sub & 1) * 8;
                        unsigned addr = smem_u32(Vc + row * SROWH + col);
                        asm volatile("ldmatrix.sync.aligned.m8n8.x4.shared.b16 {%0,%1,%2,%3}, [%4];\n"
                                     : "=r"(bf[2*np][0]), "=r"(bf[2*np][1]),
                                       "=r"(bf[2*np+1][0]), "=r"(bf[2*np+1][1])
                                     : "r"(addr));
                    }
#pragma unroll
                    for (int nf = 0; nf < 8; nf++)
                        asm volatile(
                            "mma.sync.aligned.m16n8k16.row.col.f32.f16.f16.f32 "
                            "{%0,%1,%2,%3}, {%4,%5,%6,%7}, {%8,%9}, {%0,%1,%2,%3};\n"
                            : "+f"(O[nf][0]), "+f"(O[nf][1]),
                              "+f"(O[nf][2]), "+f"(O[nf][3])
                            : "r"(a[0]), "r"(a[1]), "r"(a[2]), "r"(a[3]),
                              "r"(bf[nf][0]), "r"(bf[nf][1]));
                }
            }
            __syncthreads();
        }

        // ---- epilogue: normalize, fp16, write g_y16 [b][t][h*64+d] ----
#pragma unroll
        for (int rr = 0; rr < 2; rr++) {
            const float inv = 1.f / l[rr];
            const int t = qi * QT + warp * 16 + g + rr * 8;
            const size_t rowoff = (size_t)(b * TT + t) * DD + h * 64;
#pragma unroll
            for (int nf = 0; nf < 8; nf++) {
                const int d0 = nf * 8 + 2 * tg;
                *(__half2*)(g_y16 + rowoff + d0) =
                    __floats2half2_rn(O[nf][rr*2] * inv, O[nf][rr*2+1] * inv);
            }
        }
    }
}

// ---------------------------------------------------------------------------
extern "C" void kernel_launch(void* const* d_in, const int* in_sizes, int n_in,
                              void* d_out, int out_size)
{
    const float* x     = (const float*)d_in[0];
    const float* w_qkv = (const float*)d_in[1];
    const float* b_qkv = (const float*)d_in[2];
    const float* w_o   = (const float*)d_in[3];
    const float* b_o   = (const float*)d_in[4];
    float* out = (float*)d_out;

    const int gemm_smem  = 6 * HBUF * (int)sizeof(__half);                // 110592
    const int flash_smem = (QT + 4 * 64) * SROWH * (int)sizeof(__half);   // 55296
    cudaFuncSetAttribute(gemm_fp16<0>, cudaFuncAttributeMaxDynamicSharedMemorySize, gemm_smem);
    cudaFuncSetAttribute(gemm_fp16<1>, cudaFuncAttributeMaxDynamicSharedMemorySize, gemm_smem);
    cudaFuncSetAttribute(flash_fp16,   cudaFuncAttributeMaxDynamicSharedMemorySize, flash_smem);

    // Prep: convert x, transpose+convert weights
    conv_x_kernel<<<MROWS * DD / (256 * 4), 256>>>(x);
    {
        dim3 g1(3 * DD / 32, DD / 32);
        transpose_half_kernel<0><<<g1, 256>>>(w_qkv, DD, 3 * DD);
        dim3 g2(DD / 32, DD / 32);
        transpose_half_kernel<1><<<g2, 256>>>(w_o, DD, DD);
    }

    // QKV projection: [4096,1024] @ [1024,3072] -> q/k/v (fp16)
    {
        dim3 grid(3 * DD / 128, MROWS / 128);   // (24, 32)
        gemm_fp16<0><<<grid, 512, gemm_smem>>>(b_qkv, nullptr, 3 * DD);
    }
    // Flash attention (fp16 tensor cores, balanced two-tile blocks)
    {
        dim3 grid(8, BB * HH);                  // (8, 32) = 256 balanced CTAs
        flash_fp16<<<grid, 256, flash_smem>>>();
    }
    // Output projection: [4096,1024] @ [1024,1024] + b_o -> fp32 out
    {
        dim3 grid(DD / 128, MROWS / 128);       // (8, 32)
        gemm_fp16<1><<<grid, 512, gemm_smem>>>(b_o, out, DD);
    }
}